// round 15
// baseline (speedup 1.0000x reference)
#include <cuda_runtime.h>
#include <cuda_fp16.h>
#include <math.h>
#include <cstdint>

// Problem constants
#define T_TOK   2048
#define H_DIM   1024
#define E_NUM   16
#define I_DIM   1024
#define NPAIR   (T_TOK*2)
#define NMT     48
#define NPAD    (NMT*128)
#define WELEM   (E_NUM*I_DIM*H_DIM)

// Tiled/swizzled storage (bytes)
__device__ __align__(16) unsigned char g_gate_t[16*16*32*4096];
__device__ __align__(16) unsigned char g_up_t  [16*16*32*4096];
__device__ __align__(16) unsigned char g_down_t[16*8*32*8192];
__device__ __align__(16) unsigned char g_ax    [NMT*32*8192];
__device__ __align__(16) unsigned char g_act2  [NMT*32*8192];
__device__ int    g_expert_of[NPAIR];
__device__ float  g_weight_of[NPAIR];
__device__ int    g_base [E_NUM];
__device__ int    g_count[E_NUM];
__device__ int    g_pair_token[NPAD];
__device__ float  g_pair_w   [NPAD];

// ---------------------------------------------------------------------------
// helpers
// ---------------------------------------------------------------------------
__device__ __forceinline__ uint32_t smem_u32(const void* p) {
    uint32_t a;
    asm("{ .reg .u64 t; cvta.to.shared.u64 t, %1; cvt.u32.u64 %0, t; }" : "=r"(a) : "l"(p));
    return a;
}
__device__ __forceinline__ void ldsm_x4(uint32_t* r, uint32_t addr) {
    asm volatile("ldmatrix.sync.aligned.m8n8.x4.shared.b16 {%0,%1,%2,%3}, [%4];"
                 : "=r"(r[0]), "=r"(r[1]), "=r"(r[2]), "=r"(r[3]) : "r"(addr));
}
__device__ __forceinline__ void mma16816(float* c, const uint32_t* a, const uint32_t* b) {
    asm volatile("mma.sync.aligned.m16n8k16.row.col.f32.f16.f16.f32 "
                 "{%0,%1,%2,%3}, {%4,%5,%6,%7}, {%8,%9}, {%0,%1,%2,%3};"
                 : "+f"(c[0]), "+f"(c[1]), "+f"(c[2]), "+f"(c[3])
                 : "r"(a[0]), "r"(a[1]), "r"(a[2]), "r"(a[3]), "r"(b[0]), "r"(b[1]));
}
__device__ __forceinline__ uint32_t packh2(float x, float y) {
    __half2 h = __floats2half2_rn(x, y);
    return *(uint32_t*)&h;
}
__device__ __forceinline__ void bulk_g2s(uint32_t smem_dst, const void* gsrc,
                                         uint32_t bytes, uint32_t mbar) {
    asm volatile("cp.async.bulk.shared::cluster.global.mbarrier::complete_tx::bytes "
                 "[%0], [%1], %2, [%3];"
                 :: "r"(smem_dst), "l"(gsrc), "r"(bytes), "r"(mbar) : "memory");
}
#define FENCE_ASYNC_SHARED() \
    asm volatile("fence.proxy.async.shared::cta;" ::: "memory")
#define MBARRIER_INIT(mbar, count) \
    asm volatile("mbarrier.init.shared.b64 [%0], %1;" \
        :: "r"((uint32_t)(mbar)), "r"((uint32_t)(count)) : "memory")
#define MBARRIER_EXPECT_TX(mbar, tx) \
    asm volatile("mbarrier.arrive.expect_tx.shared.b64 _, [%0], %1;" \
        :: "r"((uint32_t)(mbar)), "r"((uint32_t)(tx)) : "memory")
#define MBARRIER_WAIT_PARITY(mbar_addr, phase_parity) do { \
    uint32_t _mbar = (uint32_t)(mbar_addr); \
    uint32_t _parity = (uint32_t)(phase_parity); \
    uint32_t _done; \
    asm volatile("{\n\t.reg .pred p;\n\t" \
        "mbarrier.try_wait.parity.acquire.cta.shared::cta.b64 p, [%1], %2;\n\t" \
        "selp.b32 %0, 1, 0, p;\n\t}" \
        : "=r"(_done) : "r"(_mbar), "r"(_parity) : "memory"); \
    if (!_done) { \
        asm volatile("{\n\t.reg .pred P1;\n\t" \
            "WAIT_LOOP_%=:\n\t" \
            "mbarrier.try_wait.parity.acquire.cta.shared::cta.b64 P1, [%0], %1, 0x989680;\n\t" \
            "@P1 bra.uni WAIT_DONE_%=;\n\t" \
            "bra.uni WAIT_LOOP_%=;\n\t" \
            "WAIT_DONE_%=:\n\t}" \
            :: "r"(_mbar), "r"(_parity) : "memory"); \
    } \
} while (0)

#define SW64K(r) (((r) & 6) << 3)
#define STAGES 4

// ---------------------------------------------------------------------------
// 0) gate/up cvt + retile + router + out zero-init
// ---------------------------------------------------------------------------
#define NCH_GU  (16*16*32*256)
#define NCH_GU2 (2*NCH_GU)
#define OUT_Q4  (T_TOK*H_DIM/4)

__global__ void cvt_gu_router_kernel(const float* __restrict__ gw,
                                     const float* __restrict__ uw,
                                     const float* __restrict__ x,
                                     const float* __restrict__ rw,
                                     float* __restrict__ out) {
    int tid = threadIdx.x;
    int g = blockIdx.x * 256 + tid;
    {
        int c = (g < NCH_GU) ? g : g - NCH_GU;
        const float* src = (g < NCH_GU) ? gw : uw;
        unsigned char* dstb = (g < NCH_GU) ? g_gate_t : g_up_t;
        int b = c >> 8, w = c & 255;
        int e = b >> 9, nt = (b >> 5) & 15, ks = b & 31;
        int rloc = w >> 2, cc = w & 3;
        int row = nt*64 + rloc;
        size_t srcoff = ((size_t)(e*1024 + row))*1024 + (ks*4 + cc)*8;
        uint32_t dstoff = (uint32_t)b*4096 + ((uint32_t)(w*16) ^ SW64K(rloc));
        float4 a = *(const float4*)(src + srcoff);
        float4 bb = *(const float4*)(src + srcoff + 4);
        uint4 o;
        o.x = packh2(a.x, a.y);  o.y = packh2(a.z, a.w);
        o.z = packh2(bb.x, bb.y); o.w = packh2(bb.z, bb.w);
        *(uint4*)(dstb + dstoff) = o;
    }

    // zero-init out (down_mma accumulates into it)
    if (g < OUT_Q4)
        ((float4*)out)[g] = make_float4(0.f, 0.f, 0.f, 0.f);

    if (blockIdx.x < T_TOK) {
        int t = blockIdx.x;
        int warp = tid >> 5, lane = tid & 31;
        __shared__ float logits[E_NUM];
        const float* xr = x + (size_t)t * H_DIM;
        const float* w0p = rw + (size_t)(2*warp)     * H_DIM;
        const float* w1p = rw + (size_t)(2*warp + 1) * H_DIM;
        float s0 = 0.f, s1 = 0.f;
        #pragma unroll 4
        for (int h = lane; h < H_DIM; h += 32) {
            float xv = xr[h];
            s0 += xv * w0p[h];
            s1 += xv * w1p[h];
        }
        #pragma unroll
        for (int o = 16; o; o >>= 1) {
            s0 += __shfl_xor_sync(0xffffffffu, s0, o);
            s1 += __shfl_xor_sync(0xffffffffu, s1, o);
        }
        if (lane == 0) { logits[2*warp] = s0; logits[2*warp + 1] = s1; }
        __syncthreads();
        if (tid == 0) {
            float sc[E_NUM];
            #pragma unroll
            for (int e = 0; e < E_NUM; e++) sc[e] = 1.f / (1.f + expf(-logits[e]));
            int i0 = 0;
            #pragma unroll
            for (int e = 1; e < E_NUM; e++) if (sc[e] > sc[i0]) i0 = e;
            int i1 = -1;
            #pragma unroll
            for (int e = 0; e < E_NUM; e++) {
                if (e == i0) continue;
                if (i1 < 0 || sc[e] > sc[i1]) i1 = e;
            }
            float w0 = sc[i0], w1 = sc[i1];
            float inv = 1.f / (w0 + w1 + 1e-20f);
            g_expert_of[2*t]   = i0;  g_weight_of[2*t]   = w0 * inv;
            g_expert_of[2*t+1] = i1;  g_weight_of[2*t+1] = w1 * inv;
        }
    }
}

// ---------------------------------------------------------------------------
// 2) Build expert-sorted padded pair lists
// ---------------------------------------------------------------------------
__global__ void build_kernel() {
    __shared__ unsigned char eid[NPAIR];
    __shared__ int cnt[E_NUM], pb[E_NUM];
    int tid = threadIdx.x;
    int w = tid >> 5, lane = tid & 31;
    for (int p = tid; p < NPAIR; p += blockDim.x)
        eid[p] = (unsigned char)g_expert_of[p];
    for (int s = tid; s < NPAD; s += blockDim.x) {
        g_pair_token[s] = 0;
        g_pair_w[s]     = 0.f;
    }
    __syncthreads();
    if (w < E_NUM) {
        int c = 0;
        for (int p0 = 0; p0 < NPAIR; p0 += 32)
            c += __popc(__ballot_sync(0xffffffffu, eid[p0 + lane] == w));
        if (lane == 0) cnt[w] = c;
    }
    __syncthreads();
    if (tid == 0) {
        int acc = 0;
        for (int e = 0; e < E_NUM; e++) {
            pb[e] = acc;
            acc += ((cnt[e] + 127) >> 7) << 7;
        }
    }
    __syncthreads();
    if (w < E_NUM) {
        int e = w, pos = pb[e];
        for (int p0 = 0; p0 < NPAIR; p0 += 32) {
            int p = p0 + lane;
            bool m = (eid[p] == e);
            unsigned mask = __ballot_sync(0xffffffffu, m);
            if (m) {
                int s = pos + __popc(mask & ((1u << lane) - 1u));
                g_pair_token[s] = p >> 1;
                g_pair_w[s]     = g_weight_of[p];
            }
            pos += __popc(mask);
        }
    }
    if (tid < E_NUM) { g_base[tid] = pb[tid]; g_count[tid] = cnt[tid]; }
}

// ---------------------------------------------------------------------------
// 2b) Gather x into tiled/swizzled fp16 layout
// ---------------------------------------------------------------------------
#define NCH_AX (NMT*32*512)

__global__ void gather_kernel(const float* __restrict__ x) {
    int g = blockIdx.x * blockDim.x + threadIdx.x;
    if (g >= NCH_AX) return;
    int mt = g >> 14, rem = g & 16383;
    int ks = rem >> 9, w = rem & 511;
    int rloc = w >> 2, cc = w & 3;
    int slot = (mt << 7) + rloc;
    int tok = g_pair_token[slot];
    const float* src = x + (size_t)tok * H_DIM + ks*32 + cc*8;
    float4 a = *(const float4*)src;
    float4 b = *(const float4*)(src + 4);
    uint4 o;
    o.x = packh2(a.x, a.y); o.y = packh2(a.z, a.w);
    o.z = packh2(b.x, b.y); o.w = packh2(b.z, b.w);
    *(uint4*)(g_ax + ((size_t)(mt*32 + ks) << 13)
                   + (((uint32_t)(w*16)) ^ SW64K(rloc))) = o;
}

// ---------------------------------------------------------------------------
// 3) gateup: syncthreads-hardened 4-stage bulk pipeline + down-cvt preamble
// ---------------------------------------------------------------------------
#define GU_TX  16384
#define GU_SMEM 66560

__global__ __launch_bounds__(256, 2)
void gateup_mma(const float* __restrict__ dw) {
    int tid = threadIdx.x, lane = tid & 31, wid = tid >> 5;

    // fused down-weight cvt
    {
        int flat = blockIdx.x + blockIdx.y * 16 + blockIdx.z * 512;
        int c = flat * 256 + tid;
        int b = c >> 9, w = c & 511;
        int e = b >> 8, nt = (b >> 5) & 7, ks = b & 31;
        int rloc = w >> 2, cc = w & 3;
        int row = nt*128 + rloc;
        size_t srcoff = ((size_t)(e*1024 + row))*1024 + (ks*4 + cc)*8;
        float4 a = *(const float4*)(dw + srcoff);
        float4 bb = *(const float4*)(dw + srcoff + 4);
        uint4 o;
        o.x = packh2(a.x, a.y);  o.y = packh2(a.z, a.w);
        o.z = packh2(bb.x, bb.y); o.w = packh2(bb.z, bb.w);
        *(uint4*)(g_down_t + (uint32_t)b*8192 + ((uint32_t)(w*16) ^ SW64K(rloc))) = o;
    }

    int e  = blockIdx.z;
    int m0 = blockIdx.y * 128;
    int bx = blockIdx.x;
    int n0 = bx * 64;
    int cnt = g_count[e];
    if (m0 >= cnt) return;
    int pb = g_base[e];

    extern __shared__ char dsm[];
    uint32_t sb = smem_u32(dsm);
    __shared__ float wrow_s[128];

    if (tid == 0) {
        #pragma unroll
        for (int s = 0; s < STAGES; s++) MBARRIER_INIT(sb + s*8, 1);
        FENCE_ASYNC_SHARED();
    }
    if (tid < 128) wrow_s[tid] = g_pair_w[pb + m0 + tid];
    __syncthreads();

    int mtg = (pb + m0) >> 7;
    const unsigned char* Asrc = g_ax     + (size_t)mtg * 32 * 8192;
    const unsigned char* Gsrc = g_gate_t + ((size_t)(e*16 + bx) * 32) * 4096;
    const unsigned char* Usrc = g_up_t   + ((size_t)(e*16 + bx) * 32) * 4096;

    int wm = wid & 3, wn = wid >> 2;
    int m_base = wm * 32, n_base = wn * 32;

    uint32_t relA[2];
    #pragma unroll
    for (int i = 0; i < 2; i++) {
        int r = m_base + i*16 + (lane & 15);
        relA[i] = (uint32_t)(r*64) + (((uint32_t)(lane >> 4) * 16) ^ SW64K(r));
    }
    uint32_t relB[2];
    #pragma unroll
    for (int jj = 0; jj < 2; jj++) {
        int r = n_base + jj*16 + (lane & 7) + (((lane >> 4) & 1) << 3);
        relB[jj] = (uint32_t)(r*64) + ((((uint32_t)(lane >> 3) & 1) * 16) ^ SW64K(r));
    }

    float cg[2][4][4] = {}, cu[2][4][4] = {};

    if (tid == 0) {
        #pragma unroll
        for (int s = 0; s < STAGES-1; s++) {
            uint32_t fb = sb + s*8;
            MBARRIER_EXPECT_TX(fb, GU_TX);
            bulk_g2s(sb + 1024  + s*8192, Asrc + (size_t)s*8192, 8192, fb);
            bulk_g2s(sb + 33792 + s*4096, Gsrc + (size_t)s*4096, 4096, fb);
            bulk_g2s(sb + 50176 + s*4096, Usrc + (size_t)s*4096, 4096, fb);
        }
    }

    const int NIT = H_DIM / 32;
    for (int it = 0; it < NIT; it++) {
        int cs = it & 3;
        MBARRIER_WAIT_PARITY(sb + cs*8, (it >> 2) & 1);
        uint32_t bA = sb + 1024 + cs*8192;
        uint32_t bG = sb + 33792 + cs*4096;
        uint32_t bU = sb + 50176 + cs*4096;
        #pragma unroll
        for (int ks = 0; ks < 2; ks++) {
            uint32_t kk = (uint32_t)ks << 5;
            uint32_t a[2][4];
            #pragma unroll
            for (int i = 0; i < 2; i++) ldsm_x4(a[i], bA + (relA[i] ^ kk));
            uint32_t bg[2][4], bu[2][4];
            #pragma unroll
            for (int jj = 0; jj < 2; jj++) {
                ldsm_x4(bg[jj], bG + (relB[jj] ^ kk));
                ldsm_x4(bu[jj], bU + (relB[jj] ^ kk));
            }
            #pragma unroll
            for (int i = 0; i < 2; i++)
                #pragma unroll
                for (int jj = 0; jj < 2; jj++) {
                    mma16816(cg[i][2*jj+0], a[i], &bg[jj][0]);
                    mma16816(cg[i][2*jj+1], a[i], &bg[jj][2]);
                    mma16816(cu[i][2*jj+0], a[i], &bu[jj][0]);
                    mma16816(cu[i][2*jj+1], a[i], &bu[jj][2]);
                }
        }
        __syncthreads();   // all consumers done with buffer cs
        if (tid == 0 && it + STAGES-1 < NIT) {
            int j = it + STAGES-1, s = j & 3;
            uint32_t fb = sb + s*8;
            MBARRIER_EXPECT_TX(fb, GU_TX);
            bulk_g2s(sb + 1024  + s*8192, Asrc + (size_t)j*8192, 8192, fb);
            bulk_g2s(sb + 33792 + s*4096, Gsrc + (size_t)j*4096, 4096, fb);
            bulk_g2s(sb + 50176 + s*4096, Usrc + (size_t)j*4096, 4096, fb);
        }
    }

    // epilogue: write ALL rows (padded rows have w=0 -> exact zeros in act2)
    int ks2 = (n0 >> 5) + wn;
    unsigned char* actb = g_act2 + ((size_t)(mtg*32 + ks2)) * 8192;
    uint32_t toff = (uint32_t)(lane & 3) * 4;
    #pragma unroll
    for (int i = 0; i < 2; i++) {
        #pragma unroll
        for (int h = 0; h < 2; h++) {
            int ml = m_base + i*16 + h*8 + (lane >> 2);
            float w = wrow_s[ml];
            uint32_t rbase = (uint32_t)(ml*64);
            uint32_t kr = SW64K(ml);
            #pragma unroll
            for (int j = 0; j < 4; j++) {
                float g0 = cg[i][j][h*2+0], g1 = cg[i][j][h*2+1];
                float u0 = cu[i][j][h*2+0], u1 = cu[i][j][h*2+1];
                float a0 = w * (g0 / (1.f + __expf(-g0))) * u0;
                float a1 = w * (g1 / (1.f + __expf(-g1))) * u1;
                uint32_t off = rbase + (((uint32_t)(j*16)) ^ kr) + toff;
                *(uint32_t*)(actb + off) = packh2(a0, a1);
            }
        }
    }
}

// ---------------------------------------------------------------------------
// 4) down: syncthreads-hardened 4-stage bulk pipeline; atomicAdd -> out
// ---------------------------------------------------------------------------
#define DN_TX  16384
#define DN_SMEM 66560

__global__ __launch_bounds__(256, 2)
void down_mma(float* __restrict__ out) {
    int e  = blockIdx.z;
    int m0 = blockIdx.y * 128;
    int bx = blockIdx.x;
    int n0 = bx * 128;
    int cnt = g_count[e];
    if (m0 >= cnt) return;
    int pb = g_base[e];

    extern __shared__ char dsm[];
    uint32_t sb = smem_u32(dsm);
    __shared__ int tok_s[128];

    int tid = threadIdx.x, lane = tid & 31, wid = tid >> 5;
    if (tid == 0) {
        #pragma unroll
        for (int s = 0; s < STAGES; s++) MBARRIER_INIT(sb + s*8, 1);
        FENCE_ASYNC_SHARED();
    }
    if (tid < 128) tok_s[tid] = g_pair_token[pb + m0 + tid];
    __syncthreads();

    int mtg = (pb + m0) >> 7;
    const unsigned char* Asrc = g_act2   + (size_t)mtg * 32 * 8192;
    const unsigned char* Bsrc = g_down_t + ((size_t)(e*8 + bx) * 32) * 8192;

    int wm = wid & 3, wn = wid >> 2;
    int m_base = wm * 32, n_base = wn * 64;

    uint32_t relA[2];
    #pragma unroll
    for (int i = 0; i < 2; i++) {
        int r = m_base + i*16 + (lane & 15);
        relA[i] = (uint32_t)(r*64) + (((uint32_t)(lane >> 4) * 16) ^ SW64K(r));
    }
    uint32_t relB[4];
    #pragma unroll
    for (int jj = 0; jj < 4; jj++) {
        int r = n_base + jj*16 + (lane & 7) + (((lane >> 4) & 1) << 3);
        relB[jj] = (uint32_t)(r*64) + ((((uint32_t)(lane >> 3) & 1) * 16) ^ SW64K(r));
    }

    float cc[2][8][4] = {};

    if (tid == 0) {
        #pragma unroll
        for (int s = 0; s < STAGES-1; s++) {
            uint32_t fb = sb + s*8;
            MBARRIER_EXPECT_TX(fb, DN_TX);
            bulk_g2s(sb + 1024  + s*8192, Asrc + (size_t)s*8192, 8192, fb);
            bulk_g2s(sb + 33792 + s*8192, Bsrc + (size_t)s*8192, 8192, fb);
        }
    }

    const int NIT = I_DIM / 32;
    for (int it = 0; it < NIT; it++) {
        int cs = it & 3;
        MBARRIER_WAIT_PARITY(sb + cs*8, (it >> 2) & 1);
        uint32_t bA = sb + 1024 + cs*8192;
        uint32_t bB = sb + 33792 + cs*8192;
        #pragma unroll
        for (int ks = 0; ks < 2; ks++) {
            uint32_t kk = (uint32_t)ks << 5;
            uint32_t a[2][4];
            #pragma unroll
            for (int i = 0; i < 2; i++) ldsm_x4(a[i], bA + (relA[i] ^ kk));
            uint32_t b[4][4];
            #pragma unroll
            for (int jj = 0; jj < 4; jj++) ldsm_x4(b[jj], bB + (relB[jj] ^ kk));
            #pragma unroll
            for (int i = 0; i < 2; i++)
                #pragma unroll
                for (int jj = 0; jj < 4; jj++) {
                    mma16816(cc[i][2*jj+0], a[i], &b[jj][0]);
                    mma16816(cc[i][2*jj+1], a[i], &b[jj][2]);
                }
        }
        __syncthreads();
        if (tid == 0 && it + STAGES-1 < NIT) {
            int j = it + STAGES-1, s = j & 3;
            uint32_t fb = sb + s*8;
            MBARRIER_EXPECT_TX(fb, DN_TX);
            bulk_g2s(sb + 1024  + s*8192, Asrc + (size_t)j*8192, 8192, fb);
            bulk_g2s(sb + 33792 + s*8192, Bsrc + (size_t)j*8192, 8192, fb);
        }
    }

    // epilogue: accumulate directly into out.
    // Each out element receives exactly 2 real contributions (one per routed
    // expert; float add commutative -> deterministic value) plus exact-0.0f
    // adds from padded rows (gateup wrote w=0 rows as exact zeros).
    #pragma unroll
    for (int i = 0; i < 2; i++) {
        #pragma unroll
        for (int h = 0; h < 2; h++) {
            int ml = m_base + i*16 + h*8 + (lane >> 2);
            float* orow = out + (size_t)tok_s[ml] * H_DIM + n0;
            #pragma unroll
            for (int j = 0; j < 8; j++) {
                int nl = n_base + j*8 + 2*(lane & 3);
                atomicAdd(&orow[nl],     cc[i][j][h*2+0]);
                atomicAdd(&orow[nl + 1], cc[i][j][h*2+1]);
            }
        }
    }
}

// ---------------------------------------------------------------------------
extern "C" void kernel_launch(void* const* d_in, const int* in_sizes, int n_in,
                              void* d_out, int out_size) {
    const float* hidden   = (const float*)d_in[0];
    const float* router_w = (const float*)d_in[1];
    const float* gate_w   = (const float*)d_in[2];
    const float* up_w     = (const float*)d_in[3];
    const float* down_w   = (const float*)d_in[4];
    float* out = (float*)d_out;

    cudaFuncSetAttribute(gateup_mma, cudaFuncAttributeMaxDynamicSharedMemorySize, GU_SMEM);
    cudaFuncSetAttribute(down_mma,   cudaFuncAttributeMaxDynamicSharedMemorySize, DN_SMEM);
    cudaFuncSetAttribute(gateup_mma, cudaFuncAttributePreferredSharedMemoryCarveout,
                         cudaSharedmemCarveoutMaxShared);
    cudaFuncSetAttribute(down_mma,   cudaFuncAttributePreferredSharedMemoryCarveout,
                         cudaSharedmemCarveoutMaxShared);

    cvt_gu_router_kernel<<<NCH_GU2/256, 256>>>(gate_w, up_w, hidden, router_w, out);
    build_kernel<<<1, 512>>>();
    gather_kernel<<<(NCH_AX + 255)/256, 256>>>(hidden);

    dim3 gridG(16, 32, E_NUM);
    gateup_mma<<<gridG, 256, GU_SMEM>>>(down_w);

    dim3 gridD(8, 32, E_NUM);
    down_mma<<<gridD, 256, DN_SMEM>>>(out);
}

// round 16
// speedup vs baseline: 1.0734x; 1.0734x over previous
#include <cuda_runtime.h>
#include <cuda_fp16.h>
#include <math.h>
#include <cstdint>

// Problem constants
#define T_TOK   2048
#define H_DIM   1024
#define E_NUM   16
#define I_DIM   1024
#define NPAIR   (T_TOK*2)
#define NMT     48
#define NPAD    (NMT*128)
#define WELEM   (E_NUM*I_DIM*H_DIM)

// Tiled/swizzled storage (bytes)
__device__ __align__(16) unsigned char g_gate_t[16*16*32*4096];
__device__ __align__(16) unsigned char g_up_t  [16*16*32*4096];
__device__ __align__(16) unsigned char g_down_t[16*8*32*8192];
__device__ __align__(16) unsigned char g_ax    [NMT*32*8192];
__device__ __align__(16) unsigned char g_act2  [NMT*32*8192];
__device__ float  g_part[NPAD * H_DIM];
__device__ int    g_expert_of[NPAIR];
__device__ float  g_weight_of[NPAIR];
__device__ int    g_base [E_NUM];
__device__ int    g_count[E_NUM];
__device__ int    g_pair_token[NPAD];
__device__ float  g_pair_w   [NPAD];
__device__ int    g_slot_of  [NPAIR];

// ---------------------------------------------------------------------------
// helpers
// ---------------------------------------------------------------------------
__device__ __forceinline__ uint32_t smem_u32(const void* p) {
    uint32_t a;
    asm("{ .reg .u64 t; cvta.to.shared.u64 t, %1; cvt.u32.u64 %0, t; }" : "=r"(a) : "l"(p));
    return a;
}
__device__ __forceinline__ void ldsm_x4(uint32_t* r, uint32_t addr) {
    asm volatile("ldmatrix.sync.aligned.m8n8.x4.shared.b16 {%0,%1,%2,%3}, [%4];"
                 : "=r"(r[0]), "=r"(r[1]), "=r"(r[2]), "=r"(r[3]) : "r"(addr));
}
__device__ __forceinline__ void mma16816(float* c, const uint32_t* a, const uint32_t* b) {
    asm volatile("mma.sync.aligned.m16n8k16.row.col.f32.f16.f16.f32 "
                 "{%0,%1,%2,%3}, {%4,%5,%6,%7}, {%8,%9}, {%0,%1,%2,%3};"
                 : "+f"(c[0]), "+f"(c[1]), "+f"(c[2]), "+f"(c[3])
                 : "r"(a[0]), "r"(a[1]), "r"(a[2]), "r"(a[3]), "r"(b[0]), "r"(b[1]));
}
__device__ __forceinline__ uint32_t packh2(float x, float y) {
    __half2 h = __floats2half2_rn(x, y);
    return *(uint32_t*)&h;
}
__device__ __forceinline__ void bulk_g2s(uint32_t smem_dst, const void* gsrc,
                                         uint32_t bytes, uint32_t mbar) {
    asm volatile("cp.async.bulk.shared::cluster.global.mbarrier::complete_tx::bytes "
                 "[%0], [%1], %2, [%3];"
                 :: "r"(smem_dst), "l"(gsrc), "r"(bytes), "r"(mbar) : "memory");
}
#define FENCE_ASYNC_SHARED() \
    asm volatile("fence.proxy.async.shared::cta;" ::: "memory")
#define MBARRIER_INIT(mbar, count) \
    asm volatile("mbarrier.init.shared.b64 [%0], %1;" \
        :: "r"((uint32_t)(mbar)), "r"((uint32_t)(count)) : "memory")
#define MBARRIER_EXPECT_TX(mbar, tx) \
    asm volatile("mbarrier.arrive.expect_tx.shared.b64 _, [%0], %1;" \
        :: "r"((uint32_t)(mbar)), "r"((uint32_t)(tx)) : "memory")
#define MBARRIER_WAIT_PARITY(mbar_addr, phase_parity) do { \
    uint32_t _mbar = (uint32_t)(mbar_addr); \
    uint32_t _parity = (uint32_t)(phase_parity); \
    uint32_t _done; \
    asm volatile("{\n\t.reg .pred p;\n\t" \
        "mbarrier.try_wait.parity.acquire.cta.shared::cta.b64 p, [%1], %2;\n\t" \
        "selp.b32 %0, 1, 0, p;\n\t}" \
        : "=r"(_done) : "r"(_mbar), "r"(_parity) : "memory"); \
    if (!_done) { \
        asm volatile("{\n\t.reg .pred P1;\n\t" \
            "WAIT_LOOP_%=:\n\t" \
            "mbarrier.try_wait.parity.acquire.cta.shared::cta.b64 P1, [%0], %1, 0x989680;\n\t" \
            "@P1 bra.uni WAIT_DONE_%=;\n\t" \
            "bra.uni WAIT_LOOP_%=;\n\t" \
            "WAIT_DONE_%=:\n\t}" \
            :: "r"(_mbar), "r"(_parity) : "memory"); \
    } \
} while (0)

#define SW64K(r) (((r) & 6) << 3)
#define STAGES 4

// ---------------------------------------------------------------------------
// 0) gate+up cvt (both tensors per thread: MLP 4) + retile + router
// ---------------------------------------------------------------------------
#define NCH_GU  (16*16*32*256)    // chunks per tensor; grid = NCH_GU/256 = 8192

__global__ void cvt_gu_router_kernel(const float* __restrict__ gw,
                                     const float* __restrict__ uw,
                                     const float* __restrict__ x,
                                     const float* __restrict__ rw) {
    int tid = threadIdx.x;
    int c = blockIdx.x * 256 + tid;       // chunk id, same for gate & up
    {
        int b = c >> 8, w = c & 255;
        int e = b >> 9, nt = (b >> 5) & 15, ks = b & 31;
        int rloc = w >> 2, cc = w & 3;
        int row = nt*64 + rloc;
        size_t srcoff = ((size_t)(e*1024 + row))*1024 + (ks*4 + cc)*8;
        uint32_t dstoff = (uint32_t)b*4096 + ((uint32_t)(w*16) ^ SW64K(rloc));
        // issue all 4 loads before converting (MLP 4)
        float4 ga = *(const float4*)(gw + srcoff);
        float4 gb = *(const float4*)(gw + srcoff + 4);
        float4 ua = *(const float4*)(uw + srcoff);
        float4 ub = *(const float4*)(uw + srcoff + 4);
        uint4 og, ou;
        og.x = packh2(ga.x, ga.y); og.y = packh2(ga.z, ga.w);
        og.z = packh2(gb.x, gb.y); og.w = packh2(gb.z, gb.w);
        ou.x = packh2(ua.x, ua.y); ou.y = packh2(ua.z, ua.w);
        ou.z = packh2(ub.x, ub.y); ou.w = packh2(ub.z, ub.w);
        *(uint4*)(g_gate_t + dstoff) = og;
        *(uint4*)(g_up_t   + dstoff) = ou;
    }

    // router: blocks [0, T_TOK)
    if (blockIdx.x < T_TOK) {
        int t = blockIdx.x;
        int warp = tid >> 5, lane = tid & 31;
        __shared__ float logits[E_NUM];
        const float* xr = x + (size_t)t * H_DIM;
        const float* w0p = rw + (size_t)(2*warp)     * H_DIM;
        const float* w1p = rw + (size_t)(2*warp + 1) * H_DIM;
        float s0 = 0.f, s1 = 0.f;
        #pragma unroll 4
        for (int h = lane; h < H_DIM; h += 32) {
            float xv = xr[h];
            s0 += xv * w0p[h];
            s1 += xv * w1p[h];
        }
        #pragma unroll
        for (int o = 16; o; o >>= 1) {
            s0 += __shfl_xor_sync(0xffffffffu, s0, o);
            s1 += __shfl_xor_sync(0xffffffffu, s1, o);
        }
        if (lane == 0) { logits[2*warp] = s0; logits[2*warp + 1] = s1; }
        __syncthreads();
        if (tid == 0) {
            float sc[E_NUM];
            #pragma unroll
            for (int e = 0; e < E_NUM; e++) sc[e] = 1.f / (1.f + expf(-logits[e]));
            int i0 = 0;
            #pragma unroll
            for (int e = 1; e < E_NUM; e++) if (sc[e] > sc[i0]) i0 = e;
            int i1 = -1;
            #pragma unroll
            for (int e = 0; e < E_NUM; e++) {
                if (e == i0) continue;
                if (i1 < 0 || sc[e] > sc[i1]) i1 = e;
            }
            float w0 = sc[i0], w1 = sc[i1];
            float inv = 1.f / (w0 + w1 + 1e-20f);
            g_expert_of[2*t]   = i0;  g_weight_of[2*t]   = w0 * inv;
            g_expert_of[2*t+1] = i1;  g_weight_of[2*t+1] = w1 * inv;
        }
    }
}

// ---------------------------------------------------------------------------
// 2) Build expert-sorted padded pair lists
// ---------------------------------------------------------------------------
__global__ void build_kernel() {
    __shared__ unsigned char eid[NPAIR];
    __shared__ int cnt[E_NUM], pb[E_NUM];
    int tid = threadIdx.x;
    int w = tid >> 5, lane = tid & 31;
    for (int p = tid; p < NPAIR; p += blockDim.x)
        eid[p] = (unsigned char)g_expert_of[p];
    for (int s = tid; s < NPAD; s += blockDim.x) {
        g_pair_token[s] = 0;
        g_pair_w[s]     = 0.f;
    }
    __syncthreads();
    if (w < E_NUM) {
        int c = 0;
        for (int p0 = 0; p0 < NPAIR; p0 += 32)
            c += __popc(__ballot_sync(0xffffffffu, eid[p0 + lane] == w));
        if (lane == 0) cnt[w] = c;
    }
    __syncthreads();
    if (tid == 0) {
        int acc = 0;
        for (int e = 0; e < E_NUM; e++) {
            pb[e] = acc;
            acc += ((cnt[e] + 127) >> 7) << 7;
        }
    }
    __syncthreads();
    if (w < E_NUM) {
        int e = w, pos = pb[e];
        for (int p0 = 0; p0 < NPAIR; p0 += 32) {
            int p = p0 + lane;
            bool m = (eid[p] == e);
            unsigned mask = __ballot_sync(0xffffffffu, m);
            if (m) {
                int s = pos + __popc(mask & ((1u << lane) - 1u));
                g_pair_token[s] = p >> 1;
                g_pair_w[s]     = g_weight_of[p];
                g_slot_of[p]    = s;
            }
            pos += __popc(mask);
        }
    }
    if (tid < E_NUM) { g_base[tid] = pb[tid]; g_count[tid] = cnt[tid]; }
}

// ---------------------------------------------------------------------------
// 2b) Gather x into tiled/swizzled fp16 layout
// ---------------------------------------------------------------------------
#define NCH_AX (NMT*32*512)

__global__ void gather_kernel(const float* __restrict__ x) {
    int g = blockIdx.x * blockDim.x + threadIdx.x;
    if (g >= NCH_AX) return;
    int mt = g >> 14, rem = g & 16383;
    int ks = rem >> 9, w = rem & 511;
    int rloc = w >> 2, cc = w & 3;
    int slot = (mt << 7) + rloc;
    int tok = g_pair_token[slot];
    const float* src = x + (size_t)tok * H_DIM + ks*32 + cc*8;
    float4 a = *(const float4*)src;
    float4 b = *(const float4*)(src + 4);
    uint4 o;
    o.x = packh2(a.x, a.y); o.y = packh2(a.z, a.w);
    o.z = packh2(b.x, b.y); o.w = packh2(b.z, b.w);
    *(uint4*)(g_ax + ((size_t)(mt*32 + ks) << 13)
                   + (((uint32_t)(w*16)) ^ SW64K(rloc))) = o;
}

// ---------------------------------------------------------------------------
// 3) gateup: syncthreads-hardened 4-stage bulk pipeline + down-cvt preamble
// ---------------------------------------------------------------------------
#define GU_TX  16384
#define GU_SMEM 66560

__global__ __launch_bounds__(256, 2)
void gateup_mma(const float* __restrict__ dw) {
    int tid = threadIdx.x, lane = tid & 31, wid = tid >> 5;

    // fused down-weight cvt
    {
        int flat = blockIdx.x + blockIdx.y * 16 + blockIdx.z * 512;
        int c = flat * 256 + tid;
        int b = c >> 9, w = c & 511;
        int e = b >> 8, nt = (b >> 5) & 7, ks = b & 31;
        int rloc = w >> 2, cc = w & 3;
        int row = nt*128 + rloc;
        size_t srcoff = ((size_t)(e*1024 + row))*1024 + (ks*4 + cc)*8;
        float4 a = *(const float4*)(dw + srcoff);
        float4 bb = *(const float4*)(dw + srcoff + 4);
        uint4 o;
        o.x = packh2(a.x, a.y);  o.y = packh2(a.z, a.w);
        o.z = packh2(bb.x, bb.y); o.w = packh2(bb.z, bb.w);
        *(uint4*)(g_down_t + (uint32_t)b*8192 + ((uint32_t)(w*16) ^ SW64K(rloc))) = o;
    }

    int e  = blockIdx.z;
    int m0 = blockIdx.y * 128;
    int bx = blockIdx.x;
    int n0 = bx * 64;
    int cnt = g_count[e];
    if (m0 >= cnt) return;
    int pb = g_base[e];

    extern __shared__ char dsm[];
    uint32_t sb = smem_u32(dsm);
    __shared__ float wrow_s[128];

    if (tid == 0) {
        #pragma unroll
        for (int s = 0; s < STAGES; s++) MBARRIER_INIT(sb + s*8, 1);
        FENCE_ASYNC_SHARED();
    }
    if (tid < 128) wrow_s[tid] = g_pair_w[pb + m0 + tid];
    __syncthreads();

    int mtg = (pb + m0) >> 7;
    const unsigned char* Asrc = g_ax     + (size_t)mtg * 32 * 8192;
    const unsigned char* Gsrc = g_gate_t + ((size_t)(e*16 + bx) * 32) * 4096;
    const unsigned char* Usrc = g_up_t   + ((size_t)(e*16 + bx) * 32) * 4096;

    int wm = wid & 3, wn = wid >> 2;
    int m_base = wm * 32, n_base = wn * 32;

    uint32_t relA[2];
    #pragma unroll
    for (int i = 0; i < 2; i++) {
        int r = m_base + i*16 + (lane & 15);
        relA[i] = (uint32_t)(r*64) + (((uint32_t)(lane >> 4) * 16) ^ SW64K(r));
    }
    uint32_t relB[2];
    #pragma unroll
    for (int jj = 0; jj < 2; jj++) {
        int r = n_base + jj*16 + (lane & 7) + (((lane >> 4) & 1) << 3);
        relB[jj] = (uint32_t)(r*64) + ((((uint32_t)(lane >> 3) & 1) * 16) ^ SW64K(r));
    }

    float cg[2][4][4] = {}, cu[2][4][4] = {};

    if (tid == 0) {
        #pragma unroll
        for (int s = 0; s < STAGES-1; s++) {
            uint32_t fb = sb + s*8;
            MBARRIER_EXPECT_TX(fb, GU_TX);
            bulk_g2s(sb + 1024  + s*8192, Asrc + (size_t)s*8192, 8192, fb);
            bulk_g2s(sb + 33792 + s*4096, Gsrc + (size_t)s*4096, 4096, fb);
            bulk_g2s(sb + 50176 + s*4096, Usrc + (size_t)s*4096, 4096, fb);
        }
    }

    const int NIT = H_DIM / 32;
    for (int it = 0; it < NIT; it++) {
        int cs = it & 3;
        MBARRIER_WAIT_PARITY(sb + cs*8, (it >> 2) & 1);
        uint32_t bA = sb + 1024 + cs*8192;
        uint32_t bG = sb + 33792 + cs*4096;
        uint32_t bU = sb + 50176 + cs*4096;
        #pragma unroll
        for (int ks = 0; ks < 2; ks++) {
            uint32_t kk = (uint32_t)ks << 5;
            uint32_t a[2][4];
            #pragma unroll
            for (int i = 0; i < 2; i++) ldsm_x4(a[i], bA + (relA[i] ^ kk));
            uint32_t bg[2][4], bu[2][4];
            #pragma unroll
            for (int jj = 0; jj < 2; jj++) {
                ldsm_x4(bg[jj], bG + (relB[jj] ^ kk));
                ldsm_x4(bu[jj], bU + (relB[jj] ^ kk));
            }
            #pragma unroll
            for (int i = 0; i < 2; i++)
                #pragma unroll
                for (int jj = 0; jj < 2; jj++) {
                    mma16816(cg[i][2*jj+0], a[i], &bg[jj][0]);
                    mma16816(cg[i][2*jj+1], a[i], &bg[jj][2]);
                    mma16816(cu[i][2*jj+0], a[i], &bu[jj][0]);
                    mma16816(cu[i][2*jj+1], a[i], &bu[jj][2]);
                }
        }
        __syncthreads();   // all consumers done with buffer cs
        if (tid == 0 && it + STAGES-1 < NIT) {
            int j = it + STAGES-1, s = j & 3;
            uint32_t fb = sb + s*8;
            MBARRIER_EXPECT_TX(fb, GU_TX);
            bulk_g2s(sb + 1024  + s*8192, Asrc + (size_t)j*8192, 8192, fb);
            bulk_g2s(sb + 33792 + s*4096, Gsrc + (size_t)j*4096, 4096, fb);
            bulk_g2s(sb + 50176 + s*4096, Usrc + (size_t)j*4096, 4096, fb);
        }
    }

    // epilogue: write w*silu(g)*u into down's tiled layout (skip padded rows)
    int ks2 = (n0 >> 5) + wn;
    unsigned char* actb = g_act2 + ((size_t)(mtg*32 + ks2)) * 8192;
    uint32_t toff = (uint32_t)(lane & 3) * 4;
    #pragma unroll
    for (int i = 0; i < 2; i++) {
        #pragma unroll
        for (int h = 0; h < 2; h++) {
            int ml = m_base + i*16 + h*8 + (lane >> 2);
            int m  = m0 + ml;
            if (m >= cnt) continue;
            float w = wrow_s[ml];
            uint32_t rbase = (uint32_t)(ml*64);
            uint32_t kr = SW64K(ml);
            #pragma unroll
            for (int j = 0; j < 4; j++) {
                float g0 = cg[i][j][h*2+0], g1 = cg[i][j][h*2+1];
                float u0 = cu[i][j][h*2+0], u1 = cu[i][j][h*2+1];
                float a0 = w * (g0 / (1.f + __expf(-g0))) * u0;
                float a1 = w * (g1 / (1.f + __expf(-g1))) * u1;
                uint32_t off = rbase + (((uint32_t)(j*16)) ^ kr) + toff;
                *(uint32_t*)(actb + off) = packh2(a0, a1);
            }
        }
    }
}

// ---------------------------------------------------------------------------
// 4) down: syncthreads-hardened 4-stage bulk pipeline -> g_part
// ---------------------------------------------------------------------------
#define DN_TX  16384
#define DN_SMEM 66560

__global__ __launch_bounds__(256, 2)
void down_mma() {
    int e  = blockIdx.z;
    int m0 = blockIdx.y * 128;
    int bx = blockIdx.x;
    int n0 = bx * 128;
    int cnt = g_count[e];
    if (m0 >= cnt) return;
    int pb = g_base[e];

    extern __shared__ char dsm[];
    uint32_t sb = smem_u32(dsm);

    int tid = threadIdx.x, lane = tid & 31, wid = tid >> 5;
    if (tid == 0) {
        #pragma unroll
        for (int s = 0; s < STAGES; s++) MBARRIER_INIT(sb + s*8, 1);
        FENCE_ASYNC_SHARED();
    }
    __syncthreads();

    int mtg = (pb + m0) >> 7;
    const unsigned char* Asrc = g_act2   + (size_t)mtg * 32 * 8192;
    const unsigned char* Bsrc = g_down_t + ((size_t)(e*8 + bx) * 32) * 8192;

    int wm = wid & 3, wn = wid >> 2;
    int m_base = wm * 32, n_base = wn * 64;

    uint32_t relA[2];
    #pragma unroll
    for (int i = 0; i < 2; i++) {
        int r = m_base + i*16 + (lane & 15);
        relA[i] = (uint32_t)(r*64) + (((uint32_t)(lane >> 4) * 16) ^ SW64K(r));
    }
    uint32_t relB[4];
    #pragma unroll
    for (int jj = 0; jj < 4; jj++) {
        int r = n_base + jj*16 + (lane & 7) + (((lane >> 4) & 1) << 3);
        relB[jj] = (uint32_t)(r*64) + ((((uint32_t)(lane >> 3) & 1) * 16) ^ SW64K(r));
    }

    float cc[2][8][4] = {};

    if (tid == 0) {
        #pragma unroll
        for (int s = 0; s < STAGES-1; s++) {
            uint32_t fb = sb + s*8;
            MBARRIER_EXPECT_TX(fb, DN_TX);
            bulk_g2s(sb + 1024  + s*8192, Asrc + (size_t)s*8192, 8192, fb);
            bulk_g2s(sb + 33792 + s*8192, Bsrc + (size_t)s*8192, 8192, fb);
        }
    }

    const int NIT = I_DIM / 32;
    for (int it = 0; it < NIT; it++) {
        int cs = it & 3;
        MBARRIER_WAIT_PARITY(sb + cs*8, (it >> 2) & 1);
        uint32_t bA = sb + 1024 + cs*8192;
        uint32_t bB = sb + 33792 + cs*8192;
        #pragma unroll
        for (int ks = 0; ks < 2; ks++) {
            uint32_t kk = (uint32_t)ks << 5;
            uint32_t a[2][4];
            #pragma unroll
            for (int i = 0; i < 2; i++) ldsm_x4(a[i], bA + (relA[i] ^ kk));
            uint32_t b[4][4];
            #pragma unroll
            for (int jj = 0; jj < 4; jj++) ldsm_x4(b[jj], bB + (relB[jj] ^ kk));
            #pragma unroll
            for (int i = 0; i < 2; i++)
                #pragma unroll
                for (int jj = 0; jj < 4; jj++) {
                    mma16816(cc[i][2*jj+0], a[i], &b[jj][0]);
                    mma16816(cc[i][2*jj+1], a[i], &b[jj][2]);
                }
        }
        __syncthreads();
        if (tid == 0 && it + STAGES-1 < NIT) {
            int j = it + STAGES-1, s = j & 3;
            uint32_t fb = sb + s*8;
            MBARRIER_EXPECT_TX(fb, DN_TX);
            bulk_g2s(sb + 1024  + s*8192, Asrc + (size_t)j*8192, 8192, fb);
            bulk_g2s(sb + 33792 + s*8192, Bsrc + (size_t)j*8192, 8192, fb);
        }
    }

    #pragma unroll
    for (int i = 0; i < 2; i++) {
        #pragma unroll
        for (int h = 0; h < 2; h++) {
            int ml = m_base + i*16 + h*8 + (lane >> 2);
            int m  = m0 + ml;
            if (m >= cnt) continue;
            float* prow = g_part + (size_t)(pb + m0 + ml) * H_DIM + n0;
            #pragma unroll
            for (int j = 0; j < 8; j++) {
                int nl = n_base + j*8 + 2*(lane & 3);
                *(float2*)&prow[nl] = make_float2(cc[i][j][h*2+0], cc[i][j][h*2+1]);
            }
        }
    }
}

// ---------------------------------------------------------------------------
// 5) Combine
// ---------------------------------------------------------------------------
__global__ void combine_kernel(float* __restrict__ out) {
    int t = blockIdx.x;
    int s0 = g_slot_of[2*t], s1 = g_slot_of[2*t + 1];
    const float4* p0 = (const float4*)(g_part + (size_t)s0 * H_DIM);
    const float4* p1 = (const float4*)(g_part + (size_t)s1 * H_DIM);
    float4* o = (float4*)(out + (size_t)t * H_DIM);
    for (int i = threadIdx.x; i < H_DIM / 4; i += blockDim.x) {
        float4 a = p0[i], b = p1[i];
        o[i] = make_float4(a.x + b.x, a.y + b.y, a.z + b.z, a.w + b.w);
    }
}

// ---------------------------------------------------------------------------
extern "C" void kernel_launch(void* const* d_in, const int* in_sizes, int n_in,
                              void* d_out, int out_size) {
    const float* hidden   = (const float*)d_in[0];
    const float* router_w = (const float*)d_in[1];
    const float* gate_w   = (const float*)d_in[2];
    const float* up_w     = (const float*)d_in[3];
    const float* down_w   = (const float*)d_in[4];
    float* out = (float*)d_out;

    cudaFuncSetAttribute(gateup_mma, cudaFuncAttributeMaxDynamicSharedMemorySize, GU_SMEM);
    cudaFuncSetAttribute(down_mma,   cudaFuncAttributeMaxDynamicSharedMemorySize, DN_SMEM);
    cudaFuncSetAttribute(gateup_mma, cudaFuncAttributePreferredSharedMemoryCarveout,
                         cudaSharedmemCarveoutMaxShared);
    cudaFuncSetAttribute(down_mma,   cudaFuncAttributePreferredSharedMemoryCarveout,
                         cudaSharedmemCarveoutMaxShared);

    cvt_gu_router_kernel<<<NCH_GU/256, 256>>>(gate_w, up_w, hidden, router_w);
    build_kernel<<<1, 512>>>();
    gather_kernel<<<(NCH_AX + 255)/256, 256>>>(hidden);

    dim3 gridG(16, 32, E_NUM);
    gateup_mma<<<gridG, 256, GU_SMEM>>>(down_w);

    dim3 gridD(8, 32, E_NUM);
    down_mma<<<gridD, 256, DN_SMEM>>>();

    combine_kernel<<<T_TOK, 256>>>(out);
}

// round 17
// speedup vs baseline: 1.0849x; 1.0107x over previous
#include <cuda_runtime.h>
#include <cuda_fp16.h>
#include <math.h>
#include <cstdint>

// Problem constants
#define T_TOK   2048
#define H_DIM   1024
#define E_NUM   16
#define I_DIM   1024
#define NPAIR   (T_TOK*2)
#define NMT     48
#define NPAD    (NMT*128)
#define WELEM   (E_NUM*I_DIM*H_DIM)

// Tiled/swizzled storage (bytes)
__device__ __align__(16) unsigned char g_gate_t[16*16*32*4096];
__device__ __align__(16) unsigned char g_up_t  [16*16*32*4096];
__device__ __align__(16) unsigned char g_down_t[16*16*32*4096];  // 64-row 4KB blocks now
__device__ __align__(16) unsigned char g_ax    [NMT*32*8192];
__device__ __align__(16) unsigned char g_act2  [NMT*32*8192];
__device__ float  g_part[NPAD * H_DIM];
__device__ int    g_expert_of[NPAIR];
__device__ float  g_weight_of[NPAIR];
__device__ int    g_base [E_NUM];
__device__ int    g_count[E_NUM];
__device__ int    g_pair_token[NPAD];
__device__ float  g_pair_w   [NPAD];
__device__ int    g_slot_of  [NPAIR];

// ---------------------------------------------------------------------------
// helpers
// ---------------------------------------------------------------------------
__device__ __forceinline__ uint32_t smem_u32(const void* p) {
    uint32_t a;
    asm("{ .reg .u64 t; cvta.to.shared.u64 t, %1; cvt.u32.u64 %0, t; }" : "=r"(a) : "l"(p));
    return a;
}
__device__ __forceinline__ void ldsm_x4(uint32_t* r, uint32_t addr) {
    asm volatile("ldmatrix.sync.aligned.m8n8.x4.shared.b16 {%0,%1,%2,%3}, [%4];"
                 : "=r"(r[0]), "=r"(r[1]), "=r"(r[2]), "=r"(r[3]) : "r"(addr));
}
__device__ __forceinline__ void mma16816(float* c, const uint32_t* a, const uint32_t* b) {
    asm volatile("mma.sync.aligned.m16n8k16.row.col.f32.f16.f16.f32 "
                 "{%0,%1,%2,%3}, {%4,%5,%6,%7}, {%8,%9}, {%0,%1,%2,%3};"
                 : "+f"(c[0]), "+f"(c[1]), "+f"(c[2]), "+f"(c[3])
                 : "r"(a[0]), "r"(a[1]), "r"(a[2]), "r"(a[3]), "r"(b[0]), "r"(b[1]));
}
__device__ __forceinline__ uint32_t packh2(float x, float y) {
    __half2 h = __floats2half2_rn(x, y);
    return *(uint32_t*)&h;
}
__device__ __forceinline__ void bulk_g2s(uint32_t smem_dst, const void* gsrc,
                                         uint32_t bytes, uint32_t mbar) {
    asm volatile("cp.async.bulk.shared::cluster.global.mbarrier::complete_tx::bytes "
                 "[%0], [%1], %2, [%3];"
                 :: "r"(smem_dst), "l"(gsrc), "r"(bytes), "r"(mbar) : "memory");
}
#define FENCE_ASYNC_SHARED() \
    asm volatile("fence.proxy.async.shared::cta;" ::: "memory")
#define MBARRIER_INIT(mbar, count) \
    asm volatile("mbarrier.init.shared.b64 [%0], %1;" \
        :: "r"((uint32_t)(mbar)), "r"((uint32_t)(count)) : "memory")
#define MBARRIER_EXPECT_TX(mbar, tx) \
    asm volatile("mbarrier.arrive.expect_tx.shared.b64 _, [%0], %1;" \
        :: "r"((uint32_t)(mbar)), "r"((uint32_t)(tx)) : "memory")
#define MBARRIER_WAIT_PARITY(mbar_addr, phase_parity) do { \
    uint32_t _mbar = (uint32_t)(mbar_addr); \
    uint32_t _parity = (uint32_t)(phase_parity); \
    uint32_t _done; \
    asm volatile("{\n\t.reg .pred p;\n\t" \
        "mbarrier.try_wait.parity.acquire.cta.shared::cta.b64 p, [%1], %2;\n\t" \
        "selp.b32 %0, 1, 0, p;\n\t}" \
        : "=r"(_done) : "r"(_mbar), "r"(_parity) : "memory"); \
    if (!_done) { \
        asm volatile("{\n\t.reg .pred P1;\n\t" \
            "WAIT_LOOP_%=:\n\t" \
            "mbarrier.try_wait.parity.acquire.cta.shared::cta.b64 P1, [%0], %1, 0x989680;\n\t" \
            "@P1 bra.uni WAIT_DONE_%=;\n\t" \
            "bra.uni WAIT_LOOP_%=;\n\t" \
            "WAIT_DONE_%=:\n\t}" \
            :: "r"(_mbar), "r"(_parity) : "memory"); \
    } \
} while (0)

#define SW64K(r) (((r) & 6) << 3)
#define STAGES 4

// ---------------------------------------------------------------------------
// 0) gate+up cvt (both tensors per thread: MLP 4) + retile + router
// ---------------------------------------------------------------------------
#define NCH_GU  (16*16*32*256)    // chunks per tensor; grid = 8192

__global__ void cvt_gu_router_kernel(const float* __restrict__ gw,
                                     const float* __restrict__ uw,
                                     const float* __restrict__ x,
                                     const float* __restrict__ rw) {
    int tid = threadIdx.x;
    int c = blockIdx.x * 256 + tid;
    {
        int b = c >> 8, w = c & 255;
        int e = b >> 9, nt = (b >> 5) & 15, ks = b & 31;
        int rloc = w >> 2, cc = w & 3;
        int row = nt*64 + rloc;
        size_t srcoff = ((size_t)(e*1024 + row))*1024 + (ks*4 + cc)*8;
        uint32_t dstoff = (uint32_t)b*4096 + ((uint32_t)(w*16) ^ SW64K(rloc));
        float4 ga = *(const float4*)(gw + srcoff);
        float4 gb = *(const float4*)(gw + srcoff + 4);
        float4 ua = *(const float4*)(uw + srcoff);
        float4 ub = *(const float4*)(uw + srcoff + 4);
        uint4 og, ou;
        og.x = packh2(ga.x, ga.y); og.y = packh2(ga.z, ga.w);
        og.z = packh2(gb.x, gb.y); og.w = packh2(gb.z, gb.w);
        ou.x = packh2(ua.x, ua.y); ou.y = packh2(ua.z, ua.w);
        ou.z = packh2(ub.x, ub.y); ou.w = packh2(ub.z, ub.w);
        *(uint4*)(g_gate_t + dstoff) = og;
        *(uint4*)(g_up_t   + dstoff) = ou;
    }

    if (blockIdx.x < T_TOK) {
        int t = blockIdx.x;
        int warp = tid >> 5, lane = tid & 31;
        __shared__ float logits[E_NUM];
        const float* xr = x + (size_t)t * H_DIM;
        const float* w0p = rw + (size_t)(2*warp)     * H_DIM;
        const float* w1p = rw + (size_t)(2*warp + 1) * H_DIM;
        float s0 = 0.f, s1 = 0.f;
        #pragma unroll 4
        for (int h = lane; h < H_DIM; h += 32) {
            float xv = xr[h];
            s0 += xv * w0p[h];
            s1 += xv * w1p[h];
        }
        #pragma unroll
        for (int o = 16; o; o >>= 1) {
            s0 += __shfl_xor_sync(0xffffffffu, s0, o);
            s1 += __shfl_xor_sync(0xffffffffu, s1, o);
        }
        if (lane == 0) { logits[2*warp] = s0; logits[2*warp + 1] = s1; }
        __syncthreads();
        if (tid == 0) {
            float sc[E_NUM];
            #pragma unroll
            for (int e = 0; e < E_NUM; e++) sc[e] = 1.f / (1.f + expf(-logits[e]));
            int i0 = 0;
            #pragma unroll
            for (int e = 1; e < E_NUM; e++) if (sc[e] > sc[i0]) i0 = e;
            int i1 = -1;
            #pragma unroll
            for (int e = 0; e < E_NUM; e++) {
                if (e == i0) continue;
                if (i1 < 0 || sc[e] > sc[i1]) i1 = e;
            }
            float w0 = sc[i0], w1 = sc[i1];
            float inv = 1.f / (w0 + w1 + 1e-20f);
            g_expert_of[2*t]   = i0;  g_weight_of[2*t]   = w0 * inv;
            g_expert_of[2*t+1] = i1;  g_weight_of[2*t+1] = w1 * inv;
        }
    }
}

// ---------------------------------------------------------------------------
// 2) Build expert-sorted padded pair lists
// ---------------------------------------------------------------------------
__global__ void build_kernel() {
    __shared__ unsigned char eid[NPAIR];
    __shared__ int cnt[E_NUM], pb[E_NUM];
    int tid = threadIdx.x;
    int w = tid >> 5, lane = tid & 31;
    for (int p = tid; p < NPAIR; p += blockDim.x)
        eid[p] = (unsigned char)g_expert_of[p];
    for (int s = tid; s < NPAD; s += blockDim.x) {
        g_pair_token[s] = 0;
        g_pair_w[s]     = 0.f;
    }
    __syncthreads();
    if (w < E_NUM) {
        int c = 0;
        for (int p0 = 0; p0 < NPAIR; p0 += 32)
            c += __popc(__ballot_sync(0xffffffffu, eid[p0 + lane] == w));
        if (lane == 0) cnt[w] = c;
    }
    __syncthreads();
    if (tid == 0) {
        int acc = 0;
        for (int e = 0; e < E_NUM; e++) {
            pb[e] = acc;
            acc += ((cnt[e] + 127) >> 7) << 7;
        }
    }
    __syncthreads();
    if (w < E_NUM) {
        int e = w, pos = pb[e];
        for (int p0 = 0; p0 < NPAIR; p0 += 32) {
            int p = p0 + lane;
            bool m = (eid[p] == e);
            unsigned mask = __ballot_sync(0xffffffffu, m);
            if (m) {
                int s = pos + __popc(mask & ((1u << lane) - 1u));
                g_pair_token[s] = p >> 1;
                g_pair_w[s]     = g_weight_of[p];
                g_slot_of[p]    = s;
            }
            pos += __popc(mask);
        }
    }
    if (tid < E_NUM) { g_base[tid] = pb[tid]; g_count[tid] = cnt[tid]; }
}

// ---------------------------------------------------------------------------
// 2b) Gather x into tiled/swizzled fp16 layout
// ---------------------------------------------------------------------------
#define NCH_AX (NMT*32*512)

__global__ void gather_kernel(const float* __restrict__ x) {
    int g = blockIdx.x * blockDim.x + threadIdx.x;
    if (g >= NCH_AX) return;
    int mt = g >> 14, rem = g & 16383;
    int ks = rem >> 9, w = rem & 511;
    int rloc = w >> 2, cc = w & 3;
    int slot = (mt << 7) + rloc;
    int tok = g_pair_token[slot];
    const float* src = x + (size_t)tok * H_DIM + ks*32 + cc*8;
    float4 a = *(const float4*)src;
    float4 b = *(const float4*)(src + 4);
    uint4 o;
    o.x = packh2(a.x, a.y); o.y = packh2(a.z, a.w);
    o.z = packh2(b.x, b.y); o.w = packh2(b.z, b.w);
    *(uint4*)(g_ax + ((size_t)(mt*32 + ks) << 13)
                   + (((uint32_t)(w*16)) ^ SW64K(rloc))) = o;
}

// ---------------------------------------------------------------------------
// 3) gateup: syncthreads-hardened 4-stage bulk pipeline + down-cvt preamble
//    (down cvt now targets 64-row 4KB blocks, same geometry as gate/up)
// ---------------------------------------------------------------------------
#define GU_TX  16384
#define GU_SMEM 66560

__global__ __launch_bounds__(256, 2)
void gateup_mma(const float* __restrict__ dw) {
    int tid = threadIdx.x, lane = tid & 31, wid = tid >> 5;

    // fused down-weight cvt -> g_down_t [e][nt16][ks32] 4KB blocks (64 rows)
    {
        int flat = blockIdx.x + blockIdx.y * 16 + blockIdx.z * 512;
        int c = flat * 256 + tid;          // [0, 2,097,152)
        int b = c >> 8, w = c & 255;
        int e = b >> 9, nt = (b >> 5) & 15, ks = b & 31;
        int rloc = w >> 2, cc = w & 3;
        int row = nt*64 + rloc;
        size_t srcoff = ((size_t)(e*1024 + row))*1024 + (ks*4 + cc)*8;
        float4 a = *(const float4*)(dw + srcoff);
        float4 bb = *(const float4*)(dw + srcoff + 4);
        uint4 o;
        o.x = packh2(a.x, a.y);  o.y = packh2(a.z, a.w);
        o.z = packh2(bb.x, bb.y); o.w = packh2(bb.z, bb.w);
        *(uint4*)(g_down_t + (uint32_t)b*4096 + ((uint32_t)(w*16) ^ SW64K(rloc))) = o;
    }

    int e  = blockIdx.z;
    int m0 = blockIdx.y * 128;
    int bx = blockIdx.x;
    int n0 = bx * 64;
    int cnt = g_count[e];
    if (m0 >= cnt) return;
    int pb = g_base[e];

    extern __shared__ char dsm[];
    uint32_t sb = smem_u32(dsm);
    __shared__ float wrow_s[128];

    if (tid == 0) {
        #pragma unroll
        for (int s = 0; s < STAGES; s++) MBARRIER_INIT(sb + s*8, 1);
        FENCE_ASYNC_SHARED();
    }
    if (tid < 128) wrow_s[tid] = g_pair_w[pb + m0 + tid];
    __syncthreads();

    int mtg = (pb + m0) >> 7;
    const unsigned char* Asrc = g_ax     + (size_t)mtg * 32 * 8192;
    const unsigned char* Gsrc = g_gate_t + ((size_t)(e*16 + bx) * 32) * 4096;
    const unsigned char* Usrc = g_up_t   + ((size_t)(e*16 + bx) * 32) * 4096;

    int wm = wid & 3, wn = wid >> 2;
    int m_base = wm * 32, n_base = wn * 32;

    uint32_t relA[2];
    #pragma unroll
    for (int i = 0; i < 2; i++) {
        int r = m_base + i*16 + (lane & 15);
        relA[i] = (uint32_t)(r*64) + (((uint32_t)(lane >> 4) * 16) ^ SW64K(r));
    }
    uint32_t relB[2];
    #pragma unroll
    for (int jj = 0; jj < 2; jj++) {
        int r = n_base + jj*16 + (lane & 7) + (((lane >> 4) & 1) << 3);
        relB[jj] = (uint32_t)(r*64) + ((((uint32_t)(lane >> 3) & 1) * 16) ^ SW64K(r));
    }

    float cg[2][4][4] = {}, cu[2][4][4] = {};

    if (tid == 0) {
        #pragma unroll
        for (int s = 0; s < STAGES-1; s++) {
            uint32_t fb = sb + s*8;
            MBARRIER_EXPECT_TX(fb, GU_TX);
            bulk_g2s(sb + 1024  + s*8192, Asrc + (size_t)s*8192, 8192, fb);
            bulk_g2s(sb + 33792 + s*4096, Gsrc + (size_t)s*4096, 4096, fb);
            bulk_g2s(sb + 50176 + s*4096, Usrc + (size_t)s*4096, 4096, fb);
        }
    }

    const int NIT = H_DIM / 32;
    for (int it = 0; it < NIT; it++) {
        int cs = it & 3;
        MBARRIER_WAIT_PARITY(sb + cs*8, (it >> 2) & 1);
        uint32_t bA = sb + 1024 + cs*8192;
        uint32_t bG = sb + 33792 + cs*4096;
        uint32_t bU = sb + 50176 + cs*4096;
        #pragma unroll
        for (int ks = 0; ks < 2; ks++) {
            uint32_t kk = (uint32_t)ks << 5;
            uint32_t a[2][4];
            #pragma unroll
            for (int i = 0; i < 2; i++) ldsm_x4(a[i], bA + (relA[i] ^ kk));
            uint32_t bg[2][4], bu[2][4];
            #pragma unroll
            for (int jj = 0; jj < 2; jj++) {
                ldsm_x4(bg[jj], bG + (relB[jj] ^ kk));
                ldsm_x4(bu[jj], bU + (relB[jj] ^ kk));
            }
            #pragma unroll
            for (int i = 0; i < 2; i++)
                #pragma unroll
                for (int jj = 0; jj < 2; jj++) {
                    mma16816(cg[i][2*jj+0], a[i], &bg[jj][0]);
                    mma16816(cg[i][2*jj+1], a[i], &bg[jj][2]);
                    mma16816(cu[i][2*jj+0], a[i], &bu[jj][0]);
                    mma16816(cu[i][2*jj+1], a[i], &bu[jj][2]);
                }
        }
        __syncthreads();
        if (tid == 0 && it + STAGES-1 < NIT) {
            int j = it + STAGES-1, s = j & 3;
            uint32_t fb = sb + s*8;
            MBARRIER_EXPECT_TX(fb, GU_TX);
            bulk_g2s(sb + 1024  + s*8192, Asrc + (size_t)j*8192, 8192, fb);
            bulk_g2s(sb + 33792 + s*4096, Gsrc + (size_t)j*4096, 4096, fb);
            bulk_g2s(sb + 50176 + s*4096, Usrc + (size_t)j*4096, 4096, fb);
        }
    }

    // epilogue
    int ks2 = (n0 >> 5) + wn;
    unsigned char* actb = g_act2 + ((size_t)(mtg*32 + ks2)) * 8192;
    uint32_t toff = (uint32_t)(lane & 3) * 4;
    #pragma unroll
    for (int i = 0; i < 2; i++) {
        #pragma unroll
        for (int h = 0; h < 2; h++) {
            int ml = m_base + i*16 + h*8 + (lane >> 2);
            int m  = m0 + ml;
            if (m >= cnt) continue;
            float w = wrow_s[ml];
            uint32_t rbase = (uint32_t)(ml*64);
            uint32_t kr = SW64K(ml);
            #pragma unroll
            for (int j = 0; j < 4; j++) {
                float g0 = cg[i][j][h*2+0], g1 = cg[i][j][h*2+1];
                float u0 = cu[i][j][h*2+0], u1 = cu[i][j][h*2+1];
                float a0 = w * (g0 / (1.f + __expf(-g0))) * u0;
                float a1 = w * (g1 / (1.f + __expf(-g1))) * u1;
                uint32_t off = rbase + (((uint32_t)(j*16)) ^ kr) + toff;
                *(uint32_t*)(actb + off) = packh2(a0, a1);
            }
        }
    }
}

// ---------------------------------------------------------------------------
// 4) down: 128M x 64N tile (wave-balanced), hardened 4-stage pipeline -> g_part
//    smem: 1024 hdr | 4x8192 A | 4x4096 B = 50176
// ---------------------------------------------------------------------------
#define DN_TX  12288
#define DN_SMEM 50176

__global__ __launch_bounds__(256, 2)
void down_mma() {
    int e  = blockIdx.z;
    int m0 = blockIdx.y * 128;
    int bx = blockIdx.x;
    int n0 = bx * 64;
    int cnt = g_count[e];
    if (m0 >= cnt) return;
    int pb = g_base[e];

    extern __shared__ char dsm[];
    uint32_t sb = smem_u32(dsm);

    int tid = threadIdx.x, lane = tid & 31, wid = tid >> 5;
    if (tid == 0) {
        #pragma unroll
        for (int s = 0; s < STAGES; s++) MBARRIER_INIT(sb + s*8, 1);
        FENCE_ASYNC_SHARED();
    }
    __syncthreads();

    int mtg = (pb + m0) >> 7;
    const unsigned char* Asrc = g_act2   + (size_t)mtg * 32 * 8192;
    const unsigned char* Bsrc = g_down_t + ((size_t)(e*16 + bx) * 32) * 4096;

    int wm = wid & 3, wn = wid >> 2;
    int m_base = wm * 32, n_base = wn * 32;

    uint32_t relA[2];
    #pragma unroll
    for (int i = 0; i < 2; i++) {
        int r = m_base + i*16 + (lane & 15);
        relA[i] = (uint32_t)(r*64) + (((uint32_t)(lane >> 4) * 16) ^ SW64K(r));
    }
    uint32_t relB[2];
    #pragma unroll
    for (int jj = 0; jj < 2; jj++) {
        int r = n_base + jj*16 + (lane & 7) + (((lane >> 4) & 1) << 3);
        relB[jj] = (uint32_t)(r*64) + ((((uint32_t)(lane >> 3) & 1) * 16) ^ SW64K(r));
    }

    float cc[2][4][4] = {};

    if (tid == 0) {
        #pragma unroll
        for (int s = 0; s < STAGES-1; s++) {
            uint32_t fb = sb + s*8;
            MBARRIER_EXPECT_TX(fb, DN_TX);
            bulk_g2s(sb + 1024  + s*8192, Asrc + (size_t)s*8192, 8192, fb);
            bulk_g2s(sb + 33792 + s*4096, Bsrc + (size_t)s*4096, 4096, fb);
        }
    }

    const int NIT = I_DIM / 32;
    for (int it = 0; it < NIT; it++) {
        int cs = it & 3;
        MBARRIER_WAIT_PARITY(sb + cs*8, (it >> 2) & 1);
        uint32_t bA = sb + 1024 + cs*8192;
        uint32_t bB = sb + 33792 + cs*4096;
        #pragma unroll
        for (int ks = 0; ks < 2; ks++) {
            uint32_t kk = (uint32_t)ks << 5;
            uint32_t a[2][4];
            #pragma unroll
            for (int i = 0; i < 2; i++) ldsm_x4(a[i], bA + (relA[i] ^ kk));
            uint32_t b[2][4];
            #pragma unroll
            for (int jj = 0; jj < 2; jj++) ldsm_x4(b[jj], bB + (relB[jj] ^ kk));
            #pragma unroll
            for (int i = 0; i < 2; i++)
                #pragma unroll
                for (int jj = 0; jj < 2; jj++) {
                    mma16816(cc[i][2*jj+0], a[i], &b[jj][0]);
                    mma16816(cc[i][2*jj+1], a[i], &b[jj][2]);
                }
        }
        __syncthreads();
        if (tid == 0 && it + STAGES-1 < NIT) {
            int j = it + STAGES-1, s = j & 3;
            uint32_t fb = sb + s*8;
            MBARRIER_EXPECT_TX(fb, DN_TX);
            bulk_g2s(sb + 1024  + s*8192, Asrc + (size_t)j*8192, 8192, fb);
            bulk_g2s(sb + 33792 + s*4096, Bsrc + (size_t)j*4096, 4096, fb);
        }
    }

    #pragma unroll
    for (int i = 0; i < 2; i++) {
        #pragma unroll
        for (int h = 0; h < 2; h++) {
            int ml = m_base + i*16 + h*8 + (lane >> 2);
            int m  = m0 + ml;
            if (m >= cnt) continue;
            float* prow = g_part + (size_t)(pb + m0 + ml) * H_DIM + n0;
            #pragma unroll
            for (int j = 0; j < 4; j++) {
                int nl = n_base + j*8 + 2*(lane & 3);
                *(float2*)&prow[nl] = make_float2(cc[i][j][h*2+0], cc[i][j][h*2+1]);
            }
        }
    }
}

// ---------------------------------------------------------------------------
// 5) Combine
// ---------------------------------------------------------------------------
__global__ void combine_kernel(float* __restrict__ out) {
    int t = blockIdx.x;
    int s0 = g_slot_of[2*t], s1 = g_slot_of[2*t + 1];
    const float4* p0 = (const float4*)(g_part + (size_t)s0 * H_DIM);
    const float4* p1 = (const float4*)(g_part + (size_t)s1 * H_DIM);
    float4* o = (float4*)(out + (size_t)t * H_DIM);
    for (int i = threadIdx.x; i < H_DIM / 4; i += blockDim.x) {
        float4 a = p0[i], b = p1[i];
        o[i] = make_float4(a.x + b.x, a.y + b.y, a.z + b.z, a.w + b.w);
    }
}

// ---------------------------------------------------------------------------
extern "C" void kernel_launch(void* const* d_in, const int* in_sizes, int n_in,
                              void* d_out, int out_size) {
    const float* hidden   = (const float*)d_in[0];
    const float* router_w = (const float*)d_in[1];
    const float* gate_w   = (const float*)d_in[2];
    const float* up_w     = (const float*)d_in[3];
    const float* down_w   = (const float*)d_in[4];
    float* out = (float*)d_out;

    cudaFuncSetAttribute(gateup_mma, cudaFuncAttributeMaxDynamicSharedMemorySize, GU_SMEM);
    cudaFuncSetAttribute(down_mma,   cudaFuncAttributeMaxDynamicSharedMemorySize, DN_SMEM);
    cudaFuncSetAttribute(gateup_mma, cudaFuncAttributePreferredSharedMemoryCarveout,
                         cudaSharedmemCarveoutMaxShared);
    cudaFuncSetAttribute(down_mma,   cudaFuncAttributePreferredSharedMemoryCarveout,
                         cudaSharedmemCarveoutMaxShared);

    cvt_gu_router_kernel<<<NCH_GU/256, 256>>>(gate_w, up_w, hidden, router_w);
    build_kernel<<<1, 512>>>();
    gather_kernel<<<(NCH_AX + 255)/256, 256>>>(hidden);

    dim3 gridG(16, 32, E_NUM);
    gateup_mma<<<gridG, 256, GU_SMEM>>>(down_w);

    dim3 gridD(16, 32, E_NUM);   // N-tiles of 64 now
    down_mma<<<gridD, 256, DN_SMEM>>>();

    combine_kernel<<<T_TOK, 256>>>(out);
}